// round 9
// baseline (speedup 1.0000x reference)
#include <cuda_runtime.h>
#include <cstdint>

#define N_NODES 50000
#define MAX_E   800000
#define D 96
#define D4 (D/4)
#define TILE_ROWS 48
#define TX 24
#define TY 8
#define RPT 6
#define XS2S 196                             // padded xs2 row stride (floats)
#define GEMM_SMEM ((D * D + TILE_ROWS * XS2S) * 4)   // 74496 B

// fused-multiply-add on packed f32x2 (FFMA2 — PTX-only on sm_103a)
#define FMA2(acc, a, b) \
    asm("fma.rn.f32x2 %0, %1, %2, %0;" : "+l"(acc) : "l"(a), "l"(b))

// ---- device scratch (zero-init at load; k_agg restores counter zeros) ----
__device__ int   g_deg_out_i[N_NODES];
__device__ int   g_deg_in_i[N_NODES];
__device__ int   g_row_ptr[N_NODES + 1];
__device__ int   g_fill[N_NODES];
__device__ int   g_csr_src[MAX_E];
__device__ float g_h[(size_t)N_NODES * D];   // (x@W) * inv_sqrt(deg_out)

// ---- kernel: degree counts (counters pre-zeroed by invariant) ----
__global__ void k_deg(const int* __restrict__ src,
                      const int* __restrict__ dst, int E) {
    int e = blockIdx.x * blockDim.x + threadIdx.x;
    if (e < E) {
        atomicAdd(&g_deg_out_i[src[e]], 1);
        atomicAdd(&g_deg_in_i[dst[e]], 1);
    }
}

// ---- kernel: single-block exclusive scan of deg_in (1024 threads) ----
__global__ __launch_bounds__(1024)
void k_scan(int E) {
    __shared__ int sh[1024];
    const int PER = (N_NODES + 1023) / 1024;   // 49
    int t = threadIdx.x;
    int beg = t * PER;
    int end = min(beg + PER, N_NODES);

    // pass 1: local segment sum
    int sum = 0;
    for (int i = beg; i < end; i++) sum += g_deg_in_i[i];
    sh[t] = sum;
    __syncthreads();

    // Hillis-Steele inclusive scan over 1024 sums
    #pragma unroll
    for (int off = 1; off < 1024; off <<= 1) {
        int v = (t >= off) ? sh[t - off] : 0;
        __syncthreads();
        sh[t] += v;
        __syncthreads();
    }
    int base = sh[t] - sum;   // exclusive prefix of my segment

    // pass 2: write prefixes (deg re-read hits L1/L2)
    int run = base;
    for (int i = beg; i < end; i++) {
        g_row_ptr[i] = run;
        g_fill[i]    = run;
        run += g_deg_in_i[i];
    }
    if (t == 1023) g_row_ptr[N_NODES] = E;
}

// ---- kernel: bucket edges by dst ----
__global__ void k_fill(const int* __restrict__ src,
                       const int* __restrict__ dst, int E) {
    int e = blockIdx.x * blockDim.x + threadIdx.x;
    if (e < E) {
        int d = dst[e];
        int pos = atomicAdd(&g_fill[d], 1);
        g_csr_src[pos] = src[e];
    }
}

// ---- kernel: h = (x@W) * inv_sqrt(deg_out), packed-f32x2 inner loop ----
__global__ __launch_bounds__(TX * TY)
void k_gemm(const float* __restrict__ x, const float* __restrict__ Wg) {
    extern __shared__ float smem[];
    float* Ws  = smem;            // [96][96]
    float* xs2 = smem + D * D;    // [48][196], x values duplicated (v,v)

    const int tid = threadIdx.y * TX + threadIdx.x;
    const int nth = TX * TY;      // 192
    const int rbase = blockIdx.x * TILE_ROWS;

    // stage W
    for (int i = tid; i < D * D / 4; i += nth)
        ((float4*)Ws)[i] = ((const float4*)Wg)[i];

    // stage x tile with per-element duplication: xs2[r][2k]=xs2[r][2k+1]=x[r][k]
    for (int i = tid; i < TILE_ROWS * D4; i += nth) {
        int r = i / D4, c = i % D4;
        int g = rbase + r;
        float4 v = make_float4(0.f, 0.f, 0.f, 0.f);
        if (g < N_NODES) v = ((const float4*)(x + (size_t)g * D))[c];
        float* p = &xs2[r * XS2S + c * 8];
        *(float4*)(p)     = make_float4(v.x, v.x, v.y, v.y);
        *(float4*)(p + 4) = make_float4(v.z, v.z, v.w, v.w);
    }
    __syncthreads();

    const int tx4 = threadIdx.x * 4;
    const int ry  = threadIdx.y * RPT;

    unsigned long long accA[RPT], accB[RPT];   // col pairs (0,1) and (2,3)
    #pragma unroll
    for (int r = 0; r < RPT; r++) { accA[r] = 0ull; accB[r] = 0ull; }

    #pragma unroll
    for (int k = 0; k < D; k += 4) {
        ulonglong2 w0 = *(const ulonglong2*)&Ws[(k + 0) * D + tx4];
        ulonglong2 w1 = *(const ulonglong2*)&Ws[(k + 1) * D + tx4];
        ulonglong2 w2 = *(const ulonglong2*)&Ws[(k + 2) * D + tx4];
        ulonglong2 w3 = *(const ulonglong2*)&Ws[(k + 3) * D + tx4];
        #pragma unroll
        for (int r = 0; r < RPT; r++) {
            const float* xr = &xs2[(ry + r) * XS2S + 2 * k];
            ulonglong2 A = *(const ulonglong2*)xr;        // (xk0,xk0),(xk1,xk1)
            ulonglong2 B = *(const ulonglong2*)(xr + 4);  // (xk2,xk2),(xk3,xk3)
            FMA2(accA[r], A.x, w0.x);  FMA2(accB[r], A.x, w0.y);
            FMA2(accA[r], A.y, w1.x);  FMA2(accB[r], A.y, w1.y);
            FMA2(accA[r], B.x, w2.x);  FMA2(accB[r], B.x, w2.y);
            FMA2(accA[r], B.y, w3.x);  FMA2(accB[r], B.y, w3.y);
        }
    }

    #pragma unroll
    for (int r = 0; r < RPT; r++) {
        int row = rbase + ry + r;
        if (row < N_NODES) {
            float dg  = (float)g_deg_out_i[row];
            float inv = dg > 0.f ? rsqrtf(dg) : 0.f;
            float a0 = __uint_as_float((unsigned)(accA[r]));
            float a1 = __uint_as_float((unsigned)(accA[r] >> 32));
            float a2 = __uint_as_float((unsigned)(accB[r]));
            float a3 = __uint_as_float((unsigned)(accB[r] >> 32));
            float4 o = make_float4(a0 * inv, a1 * inv, a2 * inv, a3 * inv);
            *(float4*)&g_h[(size_t)row * D + tx4] = o;
        }
    }
}

// ---- kernel: aggregate per dst node (one warp/node, float4 lanes) ----
__global__ __launch_bounds__(256)
void k_agg(const float* __restrict__ b, float* __restrict__ out) {
    int warp = (blockIdx.x * blockDim.x + threadIdx.x) >> 5;
    int lane = threadIdx.x & 31;
    if (warp >= N_NODES) return;

    int beg = g_row_ptr[warp];
    int end = g_row_ptr[warp + 1];

    if (lane < D4) {
        float4 a = make_float4(0.f, 0.f, 0.f, 0.f);
        const float4* hbase = (const float4*)g_h;
        int j = beg;
        for (; j + 3 < end; j += 4) {
            int s0 = __ldg(&g_csr_src[j]);
            int s1 = __ldg(&g_csr_src[j + 1]);
            int s2 = __ldg(&g_csr_src[j + 2]);
            int s3 = __ldg(&g_csr_src[j + 3]);
            float4 v0 = __ldg(hbase + (size_t)s0 * D4 + lane);
            float4 v1 = __ldg(hbase + (size_t)s1 * D4 + lane);
            float4 v2 = __ldg(hbase + (size_t)s2 * D4 + lane);
            float4 v3 = __ldg(hbase + (size_t)s3 * D4 + lane);
            a.x += (v0.x + v1.x) + (v2.x + v3.x);
            a.y += (v0.y + v1.y) + (v2.y + v3.y);
            a.z += (v0.z + v1.z) + (v2.z + v3.z);
            a.w += (v0.w + v1.w) + (v2.w + v3.w);
        }
        for (; j < end; j++) {
            int s = __ldg(&g_csr_src[j]);
            float4 v = __ldg(hbase + (size_t)s * D4 + lane);
            a.x += v.x; a.y += v.y; a.z += v.z; a.w += v.w;
        }

        float dg  = (float)g_deg_in_i[warp];
        float inv = dg > 0.f ? rsqrtf(dg) : 0.f;
        float4 bb = ((const float4*)b)[lane];
        float4 o  = make_float4(a.x * inv + bb.x, a.y * inv + bb.y,
                                a.z * inv + bb.z, a.w * inv + bb.w);
        ((float4*)(out + (size_t)warp * D))[lane] = o;
    }

    // restore zero-invariant for the next graph replay
    if (lane == 30) {
        g_deg_in_i[warp]  = 0;
        g_deg_out_i[warp] = 0;
    }
}

extern "C" void kernel_launch(void* const* d_in, const int* in_sizes, int n_in,
                              void* d_out, int out_size) {
    const float* x   = (const float*)d_in[0];
    const float* W   = (const float*)d_in[1];
    const float* b   = (const float*)d_in[2];
    const int*   src = (const int*)d_in[3];
    const int*   dst = (const int*)d_in[4];
    float* out = (float*)d_out;
    const int E = in_sizes[3];

    static bool attr_set = false;
    if (!attr_set) {
        cudaFuncSetAttribute(k_gemm, cudaFuncAttributeMaxDynamicSharedMemorySize,
                             GEMM_SMEM);
        attr_set = true;
    }

    k_deg<<<(E + 255) / 256, 256>>>(src, dst, E);
    k_scan<<<1, 1024>>>(E);
    k_fill<<<(E + 255) / 256, 256>>>(src, dst, E);
    k_gemm<<<(N_NODES + TILE_ROWS - 1) / TILE_ROWS, dim3(TX, TY), GEMM_SMEM>>>(x, W);

    long long agg_threads = (long long)N_NODES * 32;
    k_agg<<<(int)((agg_threads + 255) / 256), 256>>>(b, out);
}

// round 10
// speedup vs baseline: 2.1101x; 2.1101x over previous
#include <cuda_runtime.h>
#include <cstdint>

#define N_NODES 50000
#define MAX_E   800000
#define D 96
#define D4 (D/4)
#define TILE_ROWS 48
#define TX 24
#define TY 8
#define RPT 6
#define KH 48                                // k-phase half
#define NBLK ((N_NODES + 255) / 256)         // 196 scan blocks

// ---- device scratch (zero-init at load; k_agg restores counter zeros) ----
__device__ int   g_deg_out_i[N_NODES];
__device__ int   g_deg_in_i[N_NODES];
__device__ int   g_row_ptr[N_NODES + 1];
__device__ int   g_fill[N_NODES];
__device__ int   g_bsum[256];
__device__ int   g_csr_src[MAX_E];
__device__ float g_h[(size_t)N_NODES * D];   // (x@W) * inv_sqrt(deg_out)

// ---- kernel: degree counts (counters pre-zeroed by invariant) ----
__global__ void k_deg(const int* __restrict__ src,
                      const int* __restrict__ dst, int E) {
    int e = blockIdx.x * blockDim.x + threadIdx.x;
    if (e < E) {
        atomicAdd(&g_deg_out_i[src[e]], 1);
        atomicAdd(&g_deg_in_i[dst[e]], 1);
    }
}

// ---- scan step 1: per-block exclusive scan of deg_in ----
__global__ void k_scan1() {
    __shared__ int sh[256];
    int i = blockIdx.x * 256 + threadIdx.x;
    int v = (i < N_NODES) ? g_deg_in_i[i] : 0;
    sh[threadIdx.x] = v;
    __syncthreads();
    #pragma unroll
    for (int off = 1; off < 256; off <<= 1) {
        int t = (threadIdx.x >= off) ? sh[threadIdx.x - off] : 0;
        __syncthreads();
        sh[threadIdx.x] += t;
        __syncthreads();
    }
    if (i < N_NODES) g_row_ptr[i] = sh[threadIdx.x] - v;
    if (threadIdx.x == 255) g_bsum[blockIdx.x] = sh[255];
}

// ---- scan steps 2+3 fused: every block scans the 196 block sums itself ----
__global__ void k_scan23(int E) {
    __shared__ int sh[256];
    int t = threadIdx.x;
    int v = (t < NBLK) ? g_bsum[t] : 0;
    sh[t] = v;
    __syncthreads();
    #pragma unroll
    for (int off = 1; off < 256; off <<= 1) {
        int u = (t >= off) ? sh[t - off] : 0;
        __syncthreads();
        sh[t] += u;
        __syncthreads();
    }
    // inclusive prefix in sh; exclusive offset for this block:
    int base = (blockIdx.x > 0) ? sh[blockIdx.x - 1] : 0;

    int i = blockIdx.x * 256 + t;
    if (i < N_NODES) {
        int p = g_row_ptr[i] + base;
        g_row_ptr[i] = p;
        g_fill[i] = p;
    }
    if (i == 0) g_row_ptr[N_NODES] = E;
}

// ---- kernel: bucket edges by dst ----
__global__ void k_fill(const int* __restrict__ src,
                       const int* __restrict__ dst, int E) {
    int e = blockIdx.x * blockDim.x + threadIdx.x;
    if (e < E) {
        int d = dst[e];
        int pos = atomicAdd(&g_fill[d], 1);
        g_csr_src[pos] = src[e];
    }
}

// ---- kernel: h = (x@W) * inv_sqrt(deg_out)  (R7-proven 48-row, 2 k-phases) ----
__global__ __launch_bounds__(TX * TY)
void k_gemm(const float* __restrict__ x, const float* __restrict__ Wg) {
    __shared__ float Ws[KH * D];          // 18432 B
    __shared__ float xs[TILE_ROWS * D];   // 18432 B

    const int tid = threadIdx.y * TX + threadIdx.x;
    const int nth = TX * TY;              // 192
    const int rbase = blockIdx.x * TILE_ROWS;

    for (int i = tid; i < TILE_ROWS * D4; i += nth) {
        int r = i / D4, c = i % D4;
        int g = rbase + r;
        float4 v = make_float4(0.f, 0.f, 0.f, 0.f);
        if (g < N_NODES) v = ((const float4*)(x + (size_t)g * D))[c];
        ((float4*)xs)[r * D4 + c] = v;
    }

    float4 acc[RPT];
    #pragma unroll
    for (int r = 0; r < RPT; r++) acc[r] = make_float4(0.f, 0.f, 0.f, 0.f);

    const int tx4 = threadIdx.x * 4;
    const int ry  = threadIdx.y * RPT;

    #pragma unroll
    for (int p = 0; p < 2; p++) {
        __syncthreads();
        for (int i = tid; i < KH * D4; i += nth)
            ((float4*)Ws)[i] = ((const float4*)Wg)[p * KH * D4 + i];
        __syncthreads();

        #pragma unroll
        for (int kk = 0; kk < KH; kk += 4) {
            float4 w0 = *(const float4*)&Ws[(kk + 0) * D + tx4];
            float4 w1 = *(const float4*)&Ws[(kk + 1) * D + tx4];
            float4 w2 = *(const float4*)&Ws[(kk + 2) * D + tx4];
            float4 w3 = *(const float4*)&Ws[(kk + 3) * D + tx4];
            #pragma unroll
            for (int r = 0; r < RPT; r++) {
                float4 xv = *(const float4*)&xs[(ry + r) * D + p * KH + kk];
                acc[r].x += xv.x * w0.x + xv.y * w1.x + xv.z * w2.x + xv.w * w3.x;
                acc[r].y += xv.x * w0.y + xv.y * w1.y + xv.z * w2.y + xv.w * w3.y;
                acc[r].z += xv.x * w0.z + xv.y * w1.z + xv.z * w2.z + xv.w * w3.z;
                acc[r].w += xv.x * w0.w + xv.y * w1.w + xv.z * w2.w + xv.w * w3.w;
            }
        }
    }

    #pragma unroll
    for (int r = 0; r < RPT; r++) {
        int row = rbase + ry + r;
        if (row < N_NODES) {
            float dg  = (float)g_deg_out_i[row];
            float inv = dg > 0.f ? rsqrtf(dg) : 0.f;
            float4 o = make_float4(acc[r].x * inv, acc[r].y * inv,
                                   acc[r].z * inv, acc[r].w * inv);
            *(float4*)&g_h[(size_t)row * D + tx4] = o;
        }
    }
}

// ---- kernel: aggregate per dst node (one warp/node, float4 lanes) ----
__global__ __launch_bounds__(256)
void k_agg(const float* __restrict__ b, float* __restrict__ out) {
    int warp = (blockIdx.x * blockDim.x + threadIdx.x) >> 5;
    int lane = threadIdx.x & 31;
    if (warp >= N_NODES) return;

    int beg = g_row_ptr[warp];
    int end = g_row_ptr[warp + 1];

    if (lane < D4) {
        float4 a = make_float4(0.f, 0.f, 0.f, 0.f);
        const float4* hbase = (const float4*)g_h;
        int j = beg;
        for (; j + 3 < end; j += 4) {
            int s0 = __ldg(&g_csr_src[j]);
            int s1 = __ldg(&g_csr_src[j + 1]);
            int s2 = __ldg(&g_csr_src[j + 2]);
            int s3 = __ldg(&g_csr_src[j + 3]);
            float4 v0 = __ldg(hbase + (size_t)s0 * D4 + lane);
            float4 v1 = __ldg(hbase + (size_t)s1 * D4 + lane);
            float4 v2 = __ldg(hbase + (size_t)s2 * D4 + lane);
            float4 v3 = __ldg(hbase + (size_t)s3 * D4 + lane);
            a.x += (v0.x + v1.x) + (v2.x + v3.x);
            a.y += (v0.y + v1.y) + (v2.y + v3.y);
            a.z += (v0.z + v1.z) + (v2.z + v3.z);
            a.w += (v0.w + v1.w) + (v2.w + v3.w);
        }
        for (; j < end; j++) {
            int s = __ldg(&g_csr_src[j]);
            float4 v = __ldg(hbase + (size_t)s * D4 + lane);
            a.x += v.x; a.y += v.y; a.z += v.z; a.w += v.w;
        }

        float dg  = (float)(end - beg);            // deg_in from row_ptr
        float inv = dg > 0.f ? rsqrtf(dg) : 0.f;
        float4 bb = ((const float4*)b)[lane];
        float4 o  = make_float4(a.x * inv + bb.x, a.y * inv + bb.y,
                                a.z * inv + bb.z, a.w * inv + bb.w);
        ((float4*)(out + (size_t)warp * D))[lane] = o;
    }

    // restore zero-invariant for the next graph replay
    if (lane == 30) {
        g_deg_in_i[warp]  = 0;
        g_deg_out_i[warp] = 0;
    }
}

extern "C" void kernel_launch(void* const* d_in, const int* in_sizes, int n_in,
                              void* d_out, int out_size) {
    const float* x   = (const float*)d_in[0];
    const float* W   = (const float*)d_in[1];
    const float* b   = (const float*)d_in[2];
    const int*   src = (const int*)d_in[3];
    const int*   dst = (const int*)d_in[4];
    float* out = (float*)d_out;
    const int E = in_sizes[3];

    // fork: gemm (needs only deg_out) overlaps scan+fill (need only deg_in).
    cudaStream_t s2;
    cudaStreamCreateWithFlags(&s2, cudaStreamNonBlocking);
    cudaEvent_t ev_deg, ev_gemm;
    cudaEventCreateWithFlags(&ev_deg, cudaEventDisableTiming);
    cudaEventCreateWithFlags(&ev_gemm, cudaEventDisableTiming);

    k_deg<<<(E + 255) / 256, 256>>>(src, dst, E);
    cudaEventRecord(ev_deg, 0);

    cudaStreamWaitEvent(s2, ev_deg, 0);
    k_gemm<<<(N_NODES + TILE_ROWS - 1) / TILE_ROWS, dim3(TX, TY), 0, s2>>>(x, W);
    cudaEventRecord(ev_gemm, s2);

    k_scan1<<<NBLK, 256>>>();
    k_scan23<<<NBLK, 256>>>(E);
    k_fill<<<(E + 255) / 256, 256>>>(src, dst, E);

    cudaStreamWaitEvent(0, ev_gemm, 0);
    long long agg_threads = (long long)N_NODES * 32;
    k_agg<<<(int)((agg_threads + 255) / 256), 256>>>(b, out);
}